// round 5
// baseline (speedup 1.0000x reference)
#include <cuda_runtime.h>
#include <cstdint>

#define SEQ     8
#define HDIM    512
#define HOUT    256
#define LN_EPS  1e-5f
#define MAX_ROWS 65536

// Scratch: fused (node + pooled) vectors, [N, 512], tf32-rounded fp32 bits.
__device__ float g_fused[(size_t)MAX_ROWS * HDIM];
// Transposed + tf32-rounded out_W: [256, 512] (n-major, k-contiguous).
__device__ float g_Bt[(size_t)HOUT * HDIM];

// ---------------------------------------------------------------------------
// Helpers
// ---------------------------------------------------------------------------
__device__ __forceinline__ float warp_sum(float v) {
    #pragma unroll
    for (int o = 16; o; o >>= 1) v += __shfl_xor_sync(0xffffffffu, v, o);
    return v;
}

__device__ __forceinline__ uint32_t cvt_tf32(float f) {
    uint32_t u;
    asm("cvt.rna.tf32.f32 %0, %1;" : "=r"(u) : "f"(f));
    return u;
}

__device__ __forceinline__ uint32_t smem_u32(const void* p) {
    uint32_t a;
    asm("{ .reg .u64 t; cvta.to.shared.u64 t, %1; cvt.u32.u64 %0, t; }" : "=r"(a) : "l"(p));
    return a;
}

__device__ __forceinline__ void mma_tf32(float* d, const uint32_t* a, const uint32_t* b) {
    asm volatile(
        "mma.sync.aligned.m16n8k8.row.col.f32.tf32.tf32.f32 "
        "{%0,%1,%2,%3}, {%4,%5,%6,%7}, {%8,%9}, {%0,%1,%2,%3};"
        : "+f"(d[0]), "+f"(d[1]), "+f"(d[2]), "+f"(d[3])
        : "r"(a[0]), "r"(a[1]), "r"(a[2]), "r"(a[3]), "r"(b[0]), "r"(b[1]));
}

__device__ __forceinline__ void cp_async16(uint32_t dst, const void* src) {
    asm volatile("cp.async.cg.shared.global [%0], [%1], 16;"
                 :: "r"(dst), "l"(src) : "memory");
}
#define CP_COMMIT() asm volatile("cp.async.commit_group;" ::: "memory")
#define CP_WAIT(n)  asm volatile("cp.async.wait_group %0;" :: "n"(n) : "memory")

// ---------------------------------------------------------------------------
// Kernel A (v2): LayerNorm + attention pooling, register-resident.
//   fused = gamma ⊙ (Σ_t k_t x_t − K) + 2·beta
//   k_0 = r_0, k_j = a_j r_j, K = Σ_t k_t m_t
//   logit_j = r_j·(Σ_c γW x_j[c]) − r_j m_j·(Σ_c γW)   (constants cancel)
// 2 rows per 256-thread CTA; 4 warps per row; 128 cols per warp (float4/lane).
// ---------------------------------------------------------------------------
__global__ __launch_bounds__(256) void ln_attn_v2_kernel(
    const float* __restrict__ x,
    const float* __restrict__ gamma,
    const float* __restrict__ beta,
    const float* __restrict__ attnW)
{
    __shared__ float s_part[2][4][8][4];   // [row][slab][pos][{S,Q,P,-}]
    __shared__ float s_S1[2][4];
    __shared__ float s_k[2][8];
    __shared__ float s_K[2];

    const int tid  = threadIdx.x;
    const int w    = tid >> 5;
    const int lane = tid & 31;
    const int rloc = w >> 2;           // 0..1
    const int slab = w & 3;            // 0..3
    const size_t row = (size_t)blockIdx.x * 2 + rloc;
    const int col  = slab * 128 + lane * 4;
    const int c4   = col >> 2;

    const float4* xr = reinterpret_cast<const float4*>(x + row * SEQ * HDIM);

    const float4 gv = *reinterpret_cast<const float4*>(gamma + col);
    const float4 wn = *reinterpret_cast<const float4*>(attnW + HDIM + col);
    float4 gw;
    gw.x = gv.x * wn.x; gw.y = gv.y * wn.y; gw.z = gv.z * wn.z; gw.w = gv.w * wn.w;

    // Phase 1: load x (kept in registers), per-position partials.
    float4 xv[SEQ];
    float st[SEQ], qt[SEQ], pt[SEQ];
    #pragma unroll
    for (int t = 0; t < SEQ; t++) {
        xv[t] = xr[t * (HDIM / 4) + c4];
        const float4 v = xv[t];
        st[t] = v.x + v.y + v.z + v.w;
        qt[t] = v.x * v.x + v.y * v.y + v.z * v.z + v.w * v.w;
        pt[t] = gw.x * v.x + gw.y * v.y + gw.z * v.z + gw.w * v.w;
    }
    #pragma unroll
    for (int t = 0; t < SEQ; t++) {
        st[t] = warp_sum(st[t]);
        qt[t] = warp_sum(qt[t]);
        pt[t] = warp_sum(pt[t]);
    }
    const float s1w = warp_sum(gw.x + gw.y + gw.z + gw.w);

    #pragma unroll
    for (int t = 0; t < SEQ; t++) {
        if (lane == t) {
            s_part[rloc][slab][t][0] = st[t];
            s_part[rloc][slab][t][1] = qt[t];
            s_part[rloc][slab][t][2] = pt[t];
        }
    }
    if (lane == 8) s_S1[rloc][slab] = s1w;
    __syncthreads();

    // Phase 2: one warp per row reduces across slabs + 8-lane softmax.
    if ((w & 3) == 0) {
        const int r = rloc;
        const int t = lane & 7;
        float S = 0.f, Q = 0.f, P = 0.f, S1 = 0.f;
        #pragma unroll
        for (int sl = 0; sl < 4; sl++) {
            S  += s_part[r][sl][t][0];
            Q  += s_part[r][sl][t][1];
            P  += s_part[r][sl][t][2];
            S1 += s_S1[r][sl];
        }
        const float m    = S * (1.f / HDIM);
        const float var  = Q * (1.f / HDIM) - m * m;
        const float rstd = rsqrtf(var + LN_EPS);
        // Neighbor logits only; node (t==0) excluded from softmax.
        float logit = (t >= 1) ? rstd * (P - m * S1) : -1e30f;
        if (lane >= 8) logit = -1e30f;

        float mx = logit;
        mx = fmaxf(mx, __shfl_xor_sync(0xffffffffu, mx, 1));
        mx = fmaxf(mx, __shfl_xor_sync(0xffffffffu, mx, 2));
        mx = fmaxf(mx, __shfl_xor_sync(0xffffffffu, mx, 4));
        const float e = __expf(logit - mx);
        float se = e;
        se += __shfl_xor_sync(0xffffffffu, se, 1);
        se += __shfl_xor_sync(0xffffffffu, se, 2);
        se += __shfl_xor_sync(0xffffffffu, se, 4);
        const float a = e / se;

        const float k = (t == 0) ? rstd : a * rstd;
        float Km = k * m;
        Km += __shfl_xor_sync(0xffffffffu, Km, 1);
        Km += __shfl_xor_sync(0xffffffffu, Km, 2);
        Km += __shfl_xor_sync(0xffffffffu, Km, 4);

        if (lane < 8) s_k[r][lane] = k;
        if (lane == 0) s_K[r] = Km;
    }
    __syncthreads();

    // Phase 3: weighted combine from registers.
    float kk[SEQ];
    #pragma unroll
    for (int t = 0; t < SEQ; t++) kk[t] = s_k[rloc][t];
    const float Kc = s_K[rloc];

    float4 acc = make_float4(0.f, 0.f, 0.f, 0.f);
    #pragma unroll
    for (int t = 0; t < SEQ; t++) {
        acc.x += kk[t] * xv[t].x;
        acc.y += kk[t] * xv[t].y;
        acc.z += kk[t] * xv[t].z;
        acc.w += kk[t] * xv[t].w;
    }
    const float4 bv = *reinterpret_cast<const float4*>(beta + col);
    uint4 o;
    o.x = cvt_tf32(gv.x * (acc.x - Kc) + 2.f * bv.x);
    o.y = cvt_tf32(gv.y * (acc.y - Kc) + 2.f * bv.y);
    o.z = cvt_tf32(gv.z * (acc.z - Kc) + 2.f * bv.z);
    o.w = cvt_tf32(gv.w * (acc.w - Kc) + 2.f * bv.w);
    *reinterpret_cast<uint4*>(&g_fused[row * HDIM + col]) = o;
}

// ---------------------------------------------------------------------------
// Transpose out_W [512,256] -> g_Bt [256,512], tf32-rounded.
// ---------------------------------------------------------------------------
__global__ __launch_bounds__(256) void transpose_B_kernel(const float* __restrict__ B) {
    __shared__ float tile[32][33];
    const int n0 = blockIdx.x * 32;
    const int k0 = blockIdx.y * 32;
    const int tx = threadIdx.x & 31;
    const int ty = threadIdx.x >> 5;
    #pragma unroll
    for (int i = 0; i < 32; i += 8)
        tile[ty + i][tx] = B[(size_t)(k0 + ty + i) * HOUT + n0 + tx];
    __syncthreads();
    #pragma unroll
    for (int i = 0; i < 32; i += 8) {
        float v = tile[tx][ty + i];
        g_Bt[(size_t)(n0 + ty + i) * HDIM + k0 + tx] = __uint_as_float(cvt_tf32(v));
    }
}

// ---------------------------------------------------------------------------
// Kernel B: C = relu(A @ Bt^T + bias) via mma.sync.m16n8k8.tf32.
// CTA 128x128, BK=32, 3-stage cp.async pipeline, vectorized k-permuted frags.
// ---------------------------------------------------------------------------
#define BM 128
#define BN 128
#define BK 32
#define STAGES 3
#define A_STAGE_FLOATS (BM * BK)
#define B_STAGE_FLOATS (BN * BK)
#define STAGE_FLOATS   (A_STAGE_FLOATS + B_STAGE_FLOATS)
#define GEMM_SMEM      (STAGES * STAGE_FLOATS * 4)

__device__ __forceinline__ int swz_unit(int row, int u) {
    return row * 8 + (u ^ ((row & 1) << 2));
}

__global__ __launch_bounds__(256, 2) void gemm_v3_kernel(
    const float* __restrict__ bias,
    float* __restrict__ C)
{
    extern __shared__ float smem[];

    const int tid  = threadIdx.x;
    const int wid  = tid >> 5;
    const int lane = tid & 31;
    const int warp_m = wid & 3;
    const int warp_n = wid >> 2;
    const int g  = lane >> 2;
    const int tg = lane & 3;

    const int bn = blockIdx.x;
    const int bm = blockIdx.y;

    const float* Ag = g_fused + (size_t)bm * BM * HDIM;
    const float* Bg = g_Bt + (size_t)bn * BN * HDIM;

    const uint32_t smem_base = smem_u32(smem);

    const int st_row = tid >> 1;
    const int st_ub  = (tid & 1) * 4;

    float acc[2][8][4];
    #pragma unroll
    for (int mt = 0; mt < 2; mt++)
        #pragma unroll
        for (int nt = 0; nt < 8; nt++)
            #pragma unroll
            for (int i = 0; i < 4; i++) acc[mt][nt][i] = 0.f;

    auto stage_chunk = [&](int kchunk, int st) {
        const uint32_t sA = smem_base + (uint32_t)(st * STAGE_FLOATS) * 4u;
        const uint32_t sB = sA + A_STAGE_FLOATS * 4u;
        const float* srcA = Ag + (size_t)st_row * HDIM + kchunk * BK + st_ub * 4;
        const float* srcB = Bg + (size_t)st_row * HDIM + kchunk * BK + st_ub * 4;
        #pragma unroll
        for (int j = 0; j < 4; j++)
            cp_async16(sA + (uint32_t)swz_unit(st_row, st_ub + j) * 16u, srcA + j * 4);
        #pragma unroll
        for (int j = 0; j < 4; j++)
            cp_async16(sB + (uint32_t)swz_unit(st_row, st_ub + j) * 16u, srcB + j * 4);
    };

    #pragma unroll
    for (int s = 0; s < STAGES; s++) {
        stage_chunk(s, s);
        CP_COMMIT();
    }

    const int NCH = HDIM / BK;
    #pragma unroll 1
    for (int k = 0; k < NCH; k++) {
        const int cur = k % STAGES;
        CP_WAIT(STAGES - 1);
        __syncthreads();

        const float* Abuf = smem + cur * STAGE_FLOATS;
        const float* Bbuf = Abuf + A_STAGE_FLOATS;

        #pragma unroll
        for (int s = 0; s < 2; s++) {
            uint32_t af[4][4];
            #pragma unroll
            for (int mt = 0; mt < 2; mt++) {
                #pragma unroll
                for (int h = 0; h < 2; h++) {
                    const int r = warp_m * 32 + mt * 16 + g + h * 8;
                    const float4 v = *reinterpret_cast<const float4*>(
                        Abuf + swz_unit(r, s * 4 + tg) * 4);
                    af[mt * 2 + h][0] = __float_as_uint(v.x);
                    af[mt * 2 + h][1] = __float_as_uint(v.y);
                    af[mt * 2 + h][2] = __float_as_uint(v.z);
                    af[mt * 2 + h][3] = __float_as_uint(v.w);
                }
            }
            #pragma unroll
            for (int half = 0; half < 2; half++) {
                uint32_t bf[4][4];
                #pragma unroll
                for (int q = 0; q < 4; q++) {
                    const int n = warp_n * 64 + (half * 4 + q) * 8 + g;
                    const float4 v = *reinterpret_cast<const float4*>(
                        Bbuf + swz_unit(n, s * 4 + tg) * 4);
                    bf[q][0] = __float_as_uint(v.x);
                    bf[q][1] = __float_as_uint(v.y);
                    bf[q][2] = __float_as_uint(v.z);
                    bf[q][3] = __float_as_uint(v.w);
                }
                #pragma unroll
                for (int mt = 0; mt < 2; mt++) {
                    #pragma unroll
                    for (int q = 0; q < 4; q++) {
                        const int nt = half * 4 + q;
                        uint32_t a0[4] = { af[mt*2][0], af[mt*2+1][0],
                                           af[mt*2][1], af[mt*2+1][1] };
                        uint32_t b0[2] = { bf[q][0], bf[q][1] };
                        mma_tf32(acc[mt][nt], a0, b0);
                        uint32_t a1[4] = { af[mt*2][2], af[mt*2+1][2],
                                           af[mt*2][3], af[mt*2+1][3] };
                        uint32_t b1[2] = { bf[q][2], bf[q][3] };
                        mma_tf32(acc[mt][nt], a1, b1);
                    }
                }
            }
        }

        __syncthreads();
        if (k + STAGES < NCH) stage_chunk(k + STAGES, cur);
        CP_COMMIT();
    }

    const int row_base = bm * BM + warp_m * 32;
    const int col_base = bn * BN + warp_n * 64;
    #pragma unroll
    for (int mt = 0; mt < 2; mt++) {
        #pragma unroll
        for (int nt = 0; nt < 8; nt++) {
            const int r0 = row_base + mt * 16 + g;
            const int c0 = col_base + nt * 8 + 2 * tg;
            const float2 bb = *reinterpret_cast<const float2*>(bias + c0);
            float2 o0, o1;
            o0.x = fmaxf(acc[mt][nt][0] + bb.x, 0.f);
            o0.y = fmaxf(acc[mt][nt][1] + bb.y, 0.f);
            o1.x = fmaxf(acc[mt][nt][2] + bb.x, 0.f);
            o1.y = fmaxf(acc[mt][nt][3] + bb.y, 0.f);
            *reinterpret_cast<float2*>(C + (size_t)r0 * HOUT + c0) = o0;
            *reinterpret_cast<float2*>(C + (size_t)(r0 + 8) * HOUT + c0) = o1;
        }
    }
}

// ---------------------------------------------------------------------------
extern "C" void kernel_launch(void* const* d_in, const int* in_sizes, int n_in,
                              void* d_out, int out_size) {
    const float* x     = (const float*)d_in[0];   // [N, 8, 512]
    const float* gamma = (const float*)d_in[1];   // [512]
    const float* beta  = (const float*)d_in[2];   // [512]
    const float* attnW = (const float*)d_in[3];   // [1024, 1]
    // d_in[4] = attn_b: cancels in softmax.
    const float* outW  = (const float*)d_in[5];   // [512, 256]
    const float* outb  = (const float*)d_in[6];   // [256]
    float* out = (float*)d_out;                   // [N, 256]

    const int n = in_sizes[0] / (SEQ * HDIM);

    cudaFuncSetAttribute(gemm_v3_kernel,
                         cudaFuncAttributeMaxDynamicSharedMemorySize, GEMM_SMEM);

    ln_attn_v2_kernel<<<n / 2, 256>>>(x, gamma, beta, attnW);
    transpose_B_kernel<<<dim3(HOUT / 32, HDIM / 32), 256>>>(outW);

    dim3 grid(HOUT / BN, n / BM);
    gemm_v3_kernel<<<grid, 256, GEMM_SMEM>>>(outb, out);
}

// round 6
// speedup vs baseline: 1.0704x; 1.0704x over previous
#include <cuda_runtime.h>
#include <cstdint>

#define SEQ     8
#define HDIM    512
#define HOUT    256
#define LN_EPS  1e-5f
#define MAX_ROWS 65536

// Scratch: fused (node + pooled) vectors, [N, 512], tf32-rounded fp32 bits.
__device__ float g_fused[(size_t)MAX_ROWS * HDIM];
// Transposed + tf32-rounded out_W: [256, 512] (n-major, k-contiguous).
__device__ float g_Bt[(size_t)HOUT * HDIM];

// ---------------------------------------------------------------------------
// Helpers
// ---------------------------------------------------------------------------
__device__ __forceinline__ uint32_t cvt_tf32(float f) {
    uint32_t u;
    asm("cvt.rna.tf32.f32 %0, %1;" : "=r"(u) : "f"(f));
    return u;
}

__device__ __forceinline__ uint32_t smem_u32(const void* p) {
    uint32_t a;
    asm("{ .reg .u64 t; cvta.to.shared.u64 t, %1; cvt.u32.u64 %0, t; }" : "=r"(a) : "l"(p));
    return a;
}

__device__ __forceinline__ void mma_tf32(float* d, const uint32_t* a, const uint32_t* b) {
    asm volatile(
        "mma.sync.aligned.m16n8k8.row.col.f32.tf32.tf32.f32 "
        "{%0,%1,%2,%3}, {%4,%5,%6,%7}, {%8,%9}, {%0,%1,%2,%3};"
        : "+f"(d[0]), "+f"(d[1]), "+f"(d[2]), "+f"(d[3])
        : "r"(a[0]), "r"(a[1]), "r"(a[2]), "r"(a[3]), "r"(b[0]), "r"(b[1]));
}

__device__ __forceinline__ void cp_async16(uint32_t dst, const void* src) {
    asm volatile("cp.async.cg.shared.global [%0], [%1], 16;"
                 :: "r"(dst), "l"(src) : "memory");
}
#define CP_COMMIT() asm volatile("cp.async.commit_group;" ::: "memory")
#define CP_WAIT(n)  asm volatile("cp.async.wait_group %0;" :: "n"(n) : "memory")

// ---------------------------------------------------------------------------
// Kernel A (v3): LayerNorm + attention pooling.
// Column-owner layout (thread owns 4 cols across all 8 positions) so
// gamma/beta/attnW are read ONCE per thread; x is staged through smem
// (write-once read-once) instead of being held in registers.
//   fused = gamma ⊙ (Σ_t k_t x_t − K) + 2·beta
//   k_0 = r_0, k_j = a_j r_j, K = Σ_t k_t m_t
//   logit_j = r_j·(Σ_c γW x_j[c]) − r_j m_j·(Σ_c γW)   (constants cancel)
// 2 rows per 256-thread CTA; 4 warps per row; 128 cols per warp.
// ---------------------------------------------------------------------------
__global__ __launch_bounds__(256) void ln_attn_v3_kernel(
    const float* __restrict__ x,
    const float* __restrict__ gamma,
    const float* __restrict__ beta,
    const float* __restrict__ attnW)
{
    __shared__ float4 s_x[2][SEQ][HDIM / 4];   // 32 KB raw x tile
    __shared__ float s_part[2][4][8][4];       // [row][slab][pos][{S,Q,P,-}]
    __shared__ float s_S1[2][4];
    __shared__ float s_k[2][8];
    __shared__ float s_K[2];

    const int tid  = threadIdx.x;
    const int w    = tid >> 5;
    const int lane = tid & 31;
    const int rloc = w >> 2;           // 0..1
    const int slab = w & 3;            // 0..3
    const size_t row = (size_t)blockIdx.x * 2 + rloc;
    const int c4   = slab * 32 + lane; // float4 column index 0..127
    const int col  = c4 * 4;

    const float4* xr = reinterpret_cast<const float4*>(x + row * SEQ * HDIM);

    const float4 gv = *reinterpret_cast<const float4*>(gamma + col);
    const float4 wn = *reinterpret_cast<const float4*>(attnW + HDIM + col);
    float4 gw;
    gw.x = gv.x * wn.x; gw.y = gv.y * wn.y; gw.z = gv.z * wn.z; gw.w = gv.w * wn.w;

    // Phase 1: stream x -> smem, accumulate per-position partials.
    float st[SEQ], qt[SEQ], pt[SEQ];
    #pragma unroll
    for (int t = 0; t < SEQ; t++) {
        const float4 v = xr[t * (HDIM / 4) + c4];
        s_x[rloc][t][c4] = v;
        st[t] = v.x + v.y + v.z + v.w;
        qt[t] = v.x * v.x + v.y * v.y + v.z * v.z + v.w * v.w;
        pt[t] = gw.x * v.x + gw.y * v.y + gw.z * v.z + gw.w * v.w;
    }
    float s1w = gw.x + gw.y + gw.z + gw.w;

    // Warp reduction, round-outer for ILP across the 25 quantities.
    #pragma unroll
    for (int o = 16; o; o >>= 1) {
        #pragma unroll
        for (int t = 0; t < SEQ; t++) {
            st[t] += __shfl_xor_sync(0xffffffffu, st[t], o);
            qt[t] += __shfl_xor_sync(0xffffffffu, qt[t], o);
            pt[t] += __shfl_xor_sync(0xffffffffu, pt[t], o);
        }
        s1w += __shfl_xor_sync(0xffffffffu, s1w, o);
    }

    #pragma unroll
    for (int t = 0; t < SEQ; t++) {
        if (lane == t) {
            s_part[rloc][slab][t][0] = st[t];
            s_part[rloc][slab][t][1] = qt[t];
            s_part[rloc][slab][t][2] = pt[t];
        }
    }
    if (lane == 8) s_S1[rloc][slab] = s1w;
    __syncthreads();

    // Phase 2: one warp per row reduces across slabs + 8-lane softmax.
    if ((w & 3) == 0) {
        const int r = rloc;
        const int t = lane & 7;
        float S = 0.f, Q = 0.f, P = 0.f, S1 = 0.f;
        #pragma unroll
        for (int sl = 0; sl < 4; sl++) {
            S  += s_part[r][sl][t][0];
            Q  += s_part[r][sl][t][1];
            P  += s_part[r][sl][t][2];
            S1 += s_S1[r][sl];
        }
        const float m    = S * (1.f / HDIM);
        const float var  = Q * (1.f / HDIM) - m * m;
        const float rstd = rsqrtf(var + LN_EPS);
        float logit = (t >= 1) ? rstd * (P - m * S1) : -1e30f;
        if (lane >= 8) logit = -1e30f;

        float mx = logit;
        mx = fmaxf(mx, __shfl_xor_sync(0xffffffffu, mx, 1));
        mx = fmaxf(mx, __shfl_xor_sync(0xffffffffu, mx, 2));
        mx = fmaxf(mx, __shfl_xor_sync(0xffffffffu, mx, 4));
        const float e = __expf(logit - mx);
        float se = e;
        se += __shfl_xor_sync(0xffffffffu, se, 1);
        se += __shfl_xor_sync(0xffffffffu, se, 2);
        se += __shfl_xor_sync(0xffffffffu, se, 4);
        const float a = e / se;

        const float k = (t == 0) ? rstd : a * rstd;
        float Km = k * m;
        Km += __shfl_xor_sync(0xffffffffu, Km, 1);
        Km += __shfl_xor_sync(0xffffffffu, Km, 2);
        Km += __shfl_xor_sync(0xffffffffu, Km, 4);

        if (lane < 8) s_k[r][lane] = k;
        if (lane == 0) s_K[r] = Km;
    }
    __syncthreads();

    // Phase 3: weighted combine (LDS.128 x8), tf32 store.
    const float Kc = s_K[rloc];
    float4 acc = make_float4(0.f, 0.f, 0.f, 0.f);
    #pragma unroll
    for (int t = 0; t < SEQ; t++) {
        const float k = s_k[rloc][t];
        const float4 v = s_x[rloc][t][c4];
        acc.x += k * v.x;
        acc.y += k * v.y;
        acc.z += k * v.z;
        acc.w += k * v.w;
    }
    const float4 bv = *reinterpret_cast<const float4*>(beta + col);
    uint4 o;
    o.x = cvt_tf32(gv.x * (acc.x - Kc) + 2.f * bv.x);
    o.y = cvt_tf32(gv.y * (acc.y - Kc) + 2.f * bv.y);
    o.z = cvt_tf32(gv.z * (acc.z - Kc) + 2.f * bv.z);
    o.w = cvt_tf32(gv.w * (acc.w - Kc) + 2.f * bv.w);
    *reinterpret_cast<uint4*>(&g_fused[row * HDIM + col]) = o;
}

// ---------------------------------------------------------------------------
// Transpose out_W [512,256] -> g_Bt [256,512], tf32-rounded.
// ---------------------------------------------------------------------------
__global__ __launch_bounds__(256) void transpose_B_kernel(const float* __restrict__ B) {
    __shared__ float tile[32][33];
    const int n0 = blockIdx.x * 32;
    const int k0 = blockIdx.y * 32;
    const int tx = threadIdx.x & 31;
    const int ty = threadIdx.x >> 5;
    #pragma unroll
    for (int i = 0; i < 32; i += 8)
        tile[ty + i][tx] = B[(size_t)(k0 + ty + i) * HOUT + n0 + tx];
    __syncthreads();
    #pragma unroll
    for (int i = 0; i < 32; i += 8) {
        float v = tile[tx][ty + i];
        g_Bt[(size_t)(n0 + ty + i) * HDIM + k0 + tx] = __uint_as_float(cvt_tf32(v));
    }
}

// ---------------------------------------------------------------------------
// Kernel B: C = relu(A @ Bt^T + bias) via mma.sync.m16n8k8.tf32.
// CTA 128x128, BK=32, 3-stage cp.async pipeline, vectorized k-permuted frags.
// ---------------------------------------------------------------------------
#define BM 128
#define BN 128
#define BK 32
#define STAGES 3
#define A_STAGE_FLOATS (BM * BK)
#define B_STAGE_FLOATS (BN * BK)
#define STAGE_FLOATS   (A_STAGE_FLOATS + B_STAGE_FLOATS)
#define GEMM_SMEM      (STAGES * STAGE_FLOATS * 4)

__device__ __forceinline__ int swz_unit(int row, int u) {
    return row * 8 + (u ^ ((row & 1) << 2));
}

__global__ __launch_bounds__(256, 2) void gemm_v3_kernel(
    const float* __restrict__ bias,
    float* __restrict__ C)
{
    extern __shared__ float smem[];

    const int tid  = threadIdx.x;
    const int wid  = tid >> 5;
    const int lane = tid & 31;
    const int warp_m = wid & 3;
    const int warp_n = wid >> 2;
    const int g  = lane >> 2;
    const int tg = lane & 3;

    const int bn = blockIdx.x;
    const int bm = blockIdx.y;

    const float* Ag = g_fused + (size_t)bm * BM * HDIM;
    const float* Bg = g_Bt + (size_t)bn * BN * HDIM;

    const uint32_t smem_base = smem_u32(smem);

    const int st_row = tid >> 1;
    const int st_ub  = (tid & 1) * 4;

    float acc[2][8][4];
    #pragma unroll
    for (int mt = 0; mt < 2; mt++)
        #pragma unroll
        for (int nt = 0; nt < 8; nt++)
            #pragma unroll
            for (int i = 0; i < 4; i++) acc[mt][nt][i] = 0.f;

    auto stage_chunk = [&](int kchunk, int st) {
        const uint32_t sA = smem_base + (uint32_t)(st * STAGE_FLOATS) * 4u;
        const uint32_t sB = sA + A_STAGE_FLOATS * 4u;
        const float* srcA = Ag + (size_t)st_row * HDIM + kchunk * BK + st_ub * 4;
        const float* srcB = Bg + (size_t)st_row * HDIM + kchunk * BK + st_ub * 4;
        #pragma unroll
        for (int j = 0; j < 4; j++)
            cp_async16(sA + (uint32_t)swz_unit(st_row, st_ub + j) * 16u, srcA + j * 4);
        #pragma unroll
        for (int j = 0; j < 4; j++)
            cp_async16(sB + (uint32_t)swz_unit(st_row, st_ub + j) * 16u, srcB + j * 4);
    };

    #pragma unroll
    for (int s = 0; s < STAGES; s++) {
        stage_chunk(s, s);
        CP_COMMIT();
    }

    const int NCH = HDIM / BK;
    #pragma unroll 1
    for (int k = 0; k < NCH; k++) {
        const int cur = k % STAGES;
        CP_WAIT(STAGES - 1);
        __syncthreads();

        const float* Abuf = smem + cur * STAGE_FLOATS;
        const float* Bbuf = Abuf + A_STAGE_FLOATS;

        #pragma unroll
        for (int s = 0; s < 2; s++) {
            uint32_t af[4][4];
            #pragma unroll
            for (int mt = 0; mt < 2; mt++) {
                #pragma unroll
                for (int h = 0; h < 2; h++) {
                    const int r = warp_m * 32 + mt * 16 + g + h * 8;
                    const float4 v = *reinterpret_cast<const float4*>(
                        Abuf + swz_unit(r, s * 4 + tg) * 4);
                    af[mt * 2 + h][0] = __float_as_uint(v.x);
                    af[mt * 2 + h][1] = __float_as_uint(v.y);
                    af[mt * 2 + h][2] = __float_as_uint(v.z);
                    af[mt * 2 + h][3] = __float_as_uint(v.w);
                }
            }
            #pragma unroll
            for (int half = 0; half < 2; half++) {
                uint32_t bf[4][4];
                #pragma unroll
                for (int q = 0; q < 4; q++) {
                    const int n = warp_n * 64 + (half * 4 + q) * 8 + g;
                    const float4 v = *reinterpret_cast<const float4*>(
                        Bbuf + swz_unit(n, s * 4 + tg) * 4);
                    bf[q][0] = __float_as_uint(v.x);
                    bf[q][1] = __float_as_uint(v.y);
                    bf[q][2] = __float_as_uint(v.z);
                    bf[q][3] = __float_as_uint(v.w);
                }
                #pragma unroll
                for (int mt = 0; mt < 2; mt++) {
                    #pragma unroll
                    for (int q = 0; q < 4; q++) {
                        const int nt = half * 4 + q;
                        uint32_t a0[4] = { af[mt*2][0], af[mt*2+1][0],
                                           af[mt*2][1], af[mt*2+1][1] };
                        uint32_t b0[2] = { bf[q][0], bf[q][1] };
                        mma_tf32(acc[mt][nt], a0, b0);
                        uint32_t a1[4] = { af[mt*2][2], af[mt*2+1][2],
                                           af[mt*2][3], af[mt*2+1][3] };
                        uint32_t b1[2] = { bf[q][2], bf[q][3] };
                        mma_tf32(acc[mt][nt], a1, b1);
                    }
                }
            }
        }

        __syncthreads();
        if (k + STAGES < NCH) stage_chunk(k + STAGES, cur);
        CP_COMMIT();
    }

    const int row_base = bm * BM + warp_m * 32;
    const int col_base = bn * BN + warp_n * 64;
    #pragma unroll
    for (int mt = 0; mt < 2; mt++) {
        #pragma unroll
        for (int nt = 0; nt < 8; nt++) {
            const int r0 = row_base + mt * 16 + g;
            const int c0 = col_base + nt * 8 + 2 * tg;
            const float2 bb = *reinterpret_cast<const float2*>(bias + c0);
            float2 o0, o1;
            o0.x = fmaxf(acc[mt][nt][0] + bb.x, 0.f);
            o0.y = fmaxf(acc[mt][nt][1] + bb.y, 0.f);
            o1.x = fmaxf(acc[mt][nt][2] + bb.x, 0.f);
            o1.y = fmaxf(acc[mt][nt][3] + bb.y, 0.f);
            *reinterpret_cast<float2*>(C + (size_t)r0 * HOUT + c0) = o0;
            *reinterpret_cast<float2*>(C + (size_t)(r0 + 8) * HOUT + c0) = o1;
        }
    }
}

// ---------------------------------------------------------------------------
extern "C" void kernel_launch(void* const* d_in, const int* in_sizes, int n_in,
                              void* d_out, int out_size) {
    const float* x     = (const float*)d_in[0];   // [N, 8, 512]
    const float* gamma = (const float*)d_in[1];   // [512]
    const float* beta  = (const float*)d_in[2];   // [512]
    const float* attnW = (const float*)d_in[3];   // [1024, 1]
    // d_in[4] = attn_b: cancels in softmax.
    const float* outW  = (const float*)d_in[5];   // [512, 256]
    const float* outb  = (const float*)d_in[6];   // [256]
    float* out = (float*)d_out;                   // [N, 256]

    const int n = in_sizes[0] / (SEQ * HDIM);

    cudaFuncSetAttribute(gemm_v3_kernel,
                         cudaFuncAttributeMaxDynamicSharedMemorySize, GEMM_SMEM);

    ln_attn_v3_kernel<<<n / 2, 256>>>(x, gamma, beta, attnW);
    transpose_B_kernel<<<dim3(HOUT / 32, HDIM / 32), 256>>>(outW);

    dim3 grid(HOUT / BN, n / BM);
    gemm_v3_kernel<<<grid, 256, GEMM_SMEM>>>(outb, out);
}

// round 7
// speedup vs baseline: 1.3085x; 1.2224x over previous
#include <cuda_runtime.h>
#include <cstdint>

#define SEQ     8
#define HDIM    512
#define HOUT    256
#define LN_EPS  1e-5f
#define MAX_ROWS 65536

// Scratch: fused (node + pooled) vectors, [N, 512], tf32-rounded fp32 bits.
__device__ float g_fused[(size_t)MAX_ROWS * HDIM];
// Transposed + tf32-rounded out_W: [256, 512] (n-major, k-contiguous).
__device__ float g_Bt[(size_t)HOUT * HDIM];

// ---------------------------------------------------------------------------
// Helpers
// ---------------------------------------------------------------------------
__device__ __forceinline__ uint32_t cvt_tf32(float f) {
    uint32_t u;
    asm("cvt.rna.tf32.f32 %0, %1;" : "=r"(u) : "f"(f));
    return u;
}

__device__ __forceinline__ uint32_t smem_u32(const void* p) {
    uint32_t a;
    asm("{ .reg .u64 t; cvta.to.shared.u64 t, %1; cvt.u32.u64 %0, t; }" : "=r"(a) : "l"(p));
    return a;
}

__device__ __forceinline__ void mma_tf32(float* d, const uint32_t* a, const uint32_t* b) {
    asm volatile(
        "mma.sync.aligned.m16n8k8.row.col.f32.tf32.tf32.f32 "
        "{%0,%1,%2,%3}, {%4,%5,%6,%7}, {%8,%9}, {%0,%1,%2,%3};"
        : "+f"(d[0]), "+f"(d[1]), "+f"(d[2]), "+f"(d[3])
        : "r"(a[0]), "r"(a[1]), "r"(a[2]), "r"(a[3]), "r"(b[0]), "r"(b[1]));
}

__device__ __forceinline__ void cp_async16(uint32_t dst, const void* src) {
    asm volatile("cp.async.cg.shared.global [%0], [%1], 16;"
                 :: "r"(dst), "l"(src) : "memory");
}
#define CP_COMMIT() asm volatile("cp.async.commit_group;" ::: "memory")
#define CP_WAIT(n)  asm volatile("cp.async.wait_group %0;" :: "n"(n) : "memory")

// ---------------------------------------------------------------------------
// Kernel A (v4): LayerNorm + attention pooling, register-resident x,
// batched reduce-scatter warp reduction (31 shuffles for all 25 partials).
//   fused = gamma ⊙ (Σ_t k_t x_t − K) + 2·beta
//   k_0 = r_0, k_j = a_j r_j, K = Σ_t k_t m_t
//   logit_j = r_j·(P_j − m_j·S1),  P_j = Σ_c γW x_j[c], S1 = Σ_c γW
// One row per 256-thread CTA; thread owns 2 columns across all 8 positions.
// ---------------------------------------------------------------------------
__global__ __launch_bounds__(256) void ln_attn_v4_kernel(
    const float* __restrict__ x,
    const float* __restrict__ gamma,
    const float* __restrict__ beta,
    const float* __restrict__ attnW)
{
    __shared__ float s_red[8][26];
    __shared__ float s_k[8];
    __shared__ float s_K;

    const int tid  = threadIdx.x;
    const int w    = tid >> 5;
    const int lane = tid & 31;
    const size_t row = blockIdx.x;
    const int col = tid * 2;

    const float2* xr = reinterpret_cast<const float2*>(x + row * SEQ * HDIM);
    const float2 gv = *reinterpret_cast<const float2*>(gamma + col);
    const float2 wn = *reinterpret_cast<const float2*>(attnW + HDIM + col);
    const float2 gw = make_float2(gv.x * wn.x, gv.y * wn.y);

    // Phase 1: load x into registers, per-position local partials.
    // vals logical layout: [0..7]=S_t, [8..15]=Q_t, [16..23]=P_t, [24]=S1.
    float2 xv[SEQ];
    float vals[32];
    #pragma unroll
    for (int t = 0; t < SEQ; t++) {
        const float2 v = xr[t * (HDIM / 2) + tid];
        xv[t] = v;
        vals[t]      = v.x + v.y;
        vals[8 + t]  = v.x * v.x + v.y * v.y;
        vals[16 + t] = gw.x * v.x + gw.y * v.y;
    }
    vals[24] = gw.x + gw.y;
    #pragma unroll
    for (int j = 25; j < 32; j++) vals[j] = 0.f;

    // Batched register reduce-scatter: after 5 rounds, lane l holds the
    // warp-total of logical value l. 31 shuffles + 31 adds total.
    #pragma unroll
    for (int bit = 16; bit >= 1; bit >>= 1) {
        #pragma unroll
        for (int j = 0; j < bit; j++) {
            const bool hi = (lane & bit) != 0;
            const float keep = hi ? vals[j + bit] : vals[j];
            const float send = hi ? vals[j] : vals[j + bit];
            vals[j] = keep + __shfl_xor_sync(0xffffffffu, send, bit);
        }
    }

    if (lane < 25) s_red[w][lane] = vals[0];
    __syncthreads();

    // Phase 2: warp 0 reduces across the 8 warps and runs the softmax.
    if (w == 0) {
        float v = 0.f;
        if (lane < 25) {
            #pragma unroll
            for (int wi = 0; wi < 8; wi++) v += s_red[wi][lane];
        }
        const int t = lane & 7;
        const float S  = __shfl_sync(0xffffffffu, v, t);
        const float Q  = __shfl_sync(0xffffffffu, v, 8 + t);
        const float P  = __shfl_sync(0xffffffffu, v, 16 + t);
        const float S1 = __shfl_sync(0xffffffffu, v, 24);

        const float m    = S * (1.f / HDIM);
        const float var  = Q * (1.f / HDIM) - m * m;
        const float rstd = rsqrtf(var + LN_EPS);

        // Neighbor logits (t>=1); node and lanes>=8 masked out.
        float logit = (lane >= 1 && lane < 8) ? rstd * (P - m * S1) : -1e30f;

        float mx = logit;
        mx = fmaxf(mx, __shfl_xor_sync(0xffffffffu, mx, 1));
        mx = fmaxf(mx, __shfl_xor_sync(0xffffffffu, mx, 2));
        mx = fmaxf(mx, __shfl_xor_sync(0xffffffffu, mx, 4));
        const float e = __expf(logit - mx);
        float se = e;
        se += __shfl_xor_sync(0xffffffffu, se, 1);
        se += __shfl_xor_sync(0xffffffffu, se, 2);
        se += __shfl_xor_sync(0xffffffffu, se, 4);
        const float a = e / se;

        const float k = (lane == 0) ? rstd : a * rstd;
        float Km = k * m;
        Km += __shfl_xor_sync(0xffffffffu, Km, 1);
        Km += __shfl_xor_sync(0xffffffffu, Km, 2);
        Km += __shfl_xor_sync(0xffffffffu, Km, 4);

        if (lane < 8) s_k[lane] = k;
        if (lane == 0) s_K = Km;
    }
    __syncthreads();

    // Phase 3: register combine, tf32 store.
    const float Kc = s_K;
    float2 acc = make_float2(0.f, 0.f);
    #pragma unroll
    for (int t = 0; t < SEQ; t++) {
        const float k = s_k[t];
        acc.x += k * xv[t].x;
        acc.y += k * xv[t].y;
    }
    const float2 bv = *reinterpret_cast<const float2*>(beta + col);
    uint2 o;
    o.x = cvt_tf32(gv.x * (acc.x - Kc) + 2.f * bv.x);
    o.y = cvt_tf32(gv.y * (acc.y - Kc) + 2.f * bv.y);
    *reinterpret_cast<uint2*>(&g_fused[row * HDIM + col]) = o;
}

// ---------------------------------------------------------------------------
// Transpose out_W [512,256] -> g_Bt [256,512], tf32-rounded.
// ---------------------------------------------------------------------------
__global__ __launch_bounds__(256) void transpose_B_kernel(const float* __restrict__ B) {
    __shared__ float tile[32][33];
    const int n0 = blockIdx.x * 32;
    const int k0 = blockIdx.y * 32;
    const int tx = threadIdx.x & 31;
    const int ty = threadIdx.x >> 5;
    #pragma unroll
    for (int i = 0; i < 32; i += 8)
        tile[ty + i][tx] = B[(size_t)(k0 + ty + i) * HOUT + n0 + tx];
    __syncthreads();
    #pragma unroll
    for (int i = 0; i < 32; i += 8) {
        float v = tile[tx][ty + i];
        g_Bt[(size_t)(n0 + ty + i) * HDIM + k0 + tx] = __uint_as_float(cvt_tf32(v));
    }
}

// ---------------------------------------------------------------------------
// Kernel B: C = relu(A @ Bt^T + bias) via mma.sync.m16n8k8.tf32.
// CTA 128x128, BK=32, 3-stage cp.async pipeline, vectorized k-permuted frags.
// ---------------------------------------------------------------------------
#define BM 128
#define BN 128
#define BK 32
#define STAGES 3
#define A_STAGE_FLOATS (BM * BK)
#define B_STAGE_FLOATS (BN * BK)
#define STAGE_FLOATS   (A_STAGE_FLOATS + B_STAGE_FLOATS)
#define GEMM_SMEM      (STAGES * STAGE_FLOATS * 4)

__device__ __forceinline__ int swz_unit(int row, int u) {
    return row * 8 + (u ^ ((row & 1) << 2));
}

__global__ __launch_bounds__(256, 2) void gemm_v3_kernel(
    const float* __restrict__ bias,
    float* __restrict__ C)
{
    extern __shared__ float smem[];

    const int tid  = threadIdx.x;
    const int wid  = tid >> 5;
    const int lane = tid & 31;
    const int warp_m = wid & 3;
    const int warp_n = wid >> 2;
    const int g  = lane >> 2;
    const int tg = lane & 3;

    const int bn = blockIdx.x;
    const int bm = blockIdx.y;

    const float* Ag = g_fused + (size_t)bm * BM * HDIM;
    const float* Bg = g_Bt + (size_t)bn * BN * HDIM;

    const uint32_t smem_base = smem_u32(smem);

    const int st_row = tid >> 1;
    const int st_ub  = (tid & 1) * 4;

    float acc[2][8][4];
    #pragma unroll
    for (int mt = 0; mt < 2; mt++)
        #pragma unroll
        for (int nt = 0; nt < 8; nt++)
            #pragma unroll
            for (int i = 0; i < 4; i++) acc[mt][nt][i] = 0.f;

    auto stage_chunk = [&](int kchunk, int st) {
        const uint32_t sA = smem_base + (uint32_t)(st * STAGE_FLOATS) * 4u;
        const uint32_t sB = sA + A_STAGE_FLOATS * 4u;
        const float* srcA = Ag + (size_t)st_row * HDIM + kchunk * BK + st_ub * 4;
        const float* srcB = Bg + (size_t)st_row * HDIM + kchunk * BK + st_ub * 4;
        #pragma unroll
        for (int j = 0; j < 4; j++)
            cp_async16(sA + (uint32_t)swz_unit(st_row, st_ub + j) * 16u, srcA + j * 4);
        #pragma unroll
        for (int j = 0; j < 4; j++)
            cp_async16(sB + (uint32_t)swz_unit(st_row, st_ub + j) * 16u, srcB + j * 4);
    };

    #pragma unroll
    for (int s = 0; s < STAGES; s++) {
        stage_chunk(s, s);
        CP_COMMIT();
    }

    const int NCH = HDIM / BK;
    #pragma unroll 1
    for (int k = 0; k < NCH; k++) {
        const int cur = k % STAGES;
        CP_WAIT(STAGES - 1);
        __syncthreads();

        const float* Abuf = smem + cur * STAGE_FLOATS;
        const float* Bbuf = Abuf + A_STAGE_FLOATS;

        #pragma unroll
        for (int s = 0; s < 2; s++) {
            uint32_t af[4][4];
            #pragma unroll
            for (int mt = 0; mt < 2; mt++) {
                #pragma unroll
                for (int h = 0; h < 2; h++) {
                    const int r = warp_m * 32 + mt * 16 + g + h * 8;
                    const float4 v = *reinterpret_cast<const float4*>(
                        Abuf + swz_unit(r, s * 4 + tg) * 4);
                    af[mt * 2 + h][0] = __float_as_uint(v.x);
                    af[mt * 2 + h][1] = __float_as_uint(v.y);
                    af[mt * 2 + h][2] = __float_as_uint(v.z);
                    af[mt * 2 + h][3] = __float_as_uint(v.w);
                }
            }
            #pragma unroll
            for (int half = 0; half < 2; half++) {
                uint32_t bf[4][4];
                #pragma unroll
                for (int q = 0; q < 4; q++) {
                    const int n = warp_n * 64 + (half * 4 + q) * 8 + g;
                    const float4 v = *reinterpret_cast<const float4*>(
                        Bbuf + swz_unit(n, s * 4 + tg) * 4);
                    bf[q][0] = __float_as_uint(v.x);
                    bf[q][1] = __float_as_uint(v.y);
                    bf[q][2] = __float_as_uint(v.z);
                    bf[q][3] = __float_as_uint(v.w);
                }
                #pragma unroll
                for (int mt = 0; mt < 2; mt++) {
                    #pragma unroll
                    for (int q = 0; q < 4; q++) {
                        const int nt = half * 4 + q;
                        uint32_t a0[4] = { af[mt*2][0], af[mt*2+1][0],
                                           af[mt*2][1], af[mt*2+1][1] };
                        uint32_t b0[2] = { bf[q][0], bf[q][1] };
                        mma_tf32(acc[mt][nt], a0, b0);
                        uint32_t a1[4] = { af[mt*2][2], af[mt*2+1][2],
                                           af[mt*2][3], af[mt*2+1][3] };
                        uint32_t b1[2] = { bf[q][2], bf[q][3] };
                        mma_tf32(acc[mt][nt], a1, b1);
                    }
                }
            }
        }

        __syncthreads();
        if (k + STAGES < NCH) stage_chunk(k + STAGES, cur);
        CP_COMMIT();
    }

    const int row_base = bm * BM + warp_m * 32;
    const int col_base = bn * BN + warp_n * 64;
    #pragma unroll
    for (int mt = 0; mt < 2; mt++) {
        #pragma unroll
        for (int nt = 0; nt < 8; nt++) {
            const int r0 = row_base + mt * 16 + g;
            const int c0 = col_base + nt * 8 + 2 * tg;
            const float2 bb = *reinterpret_cast<const float2*>(bias + c0);
            float2 o0, o1;
            o0.x = fmaxf(acc[mt][nt][0] + bb.x, 0.f);
            o0.y = fmaxf(acc[mt][nt][1] + bb.y, 0.f);
            o1.x = fmaxf(acc[mt][nt][2] + bb.x, 0.f);
            o1.y = fmaxf(acc[mt][nt][3] + bb.y, 0.f);
            *reinterpret_cast<float2*>(C + (size_t)r0 * HOUT + c0) = o0;
            *reinterpret_cast<float2*>(C + (size_t)(r0 + 8) * HOUT + c0) = o1;
        }
    }
}

// ---------------------------------------------------------------------------
extern "C" void kernel_launch(void* const* d_in, const int* in_sizes, int n_in,
                              void* d_out, int out_size) {
    const float* x     = (const float*)d_in[0];   // [N, 8, 512]
    const float* gamma = (const float*)d_in[1];   // [512]
    const float* beta  = (const float*)d_in[2];   // [512]
    const float* attnW = (const float*)d_in[3];   // [1024, 1]
    // d_in[4] = attn_b: cancels in softmax.
    const float* outW  = (const float*)d_in[5];   // [512, 256]
    const float* outb  = (const float*)d_in[6];   // [256]
    float* out = (float*)d_out;                   // [N, 256]

    const int n = in_sizes[0] / (SEQ * HDIM);

    cudaFuncSetAttribute(gemm_v3_kernel,
                         cudaFuncAttributeMaxDynamicSharedMemorySize, GEMM_SMEM);

    ln_attn_v4_kernel<<<n, 256>>>(x, gamma, beta, attnW);
    transpose_B_kernel<<<dim3(HOUT / 32, HDIM / 32), 256>>>(outW);

    dim3 grid(HOUT / BN, n / BM);
    gemm_v3_kernel<<<grid, 256, GEMM_SMEM>>>(outb, out);
}

// round 8
// speedup vs baseline: 1.4097x; 1.0773x over previous
#include <cuda_runtime.h>
#include <cstdint>

#define SEQ     8
#define HDIM    512
#define HOUT    256
#define LN_EPS  1e-5f
#define MAX_ROWS 65536

// Scratch: fused (node + pooled) vectors, [N, 512], tf32-rounded fp32 bits.
__device__ float g_fused[(size_t)MAX_ROWS * HDIM];
// Transposed + tf32-rounded out_W: [256, 512] (n-major, k-contiguous).
__device__ float g_Bt[(size_t)HOUT * HDIM];

// ---------------------------------------------------------------------------
// Helpers
// ---------------------------------------------------------------------------
__device__ __forceinline__ uint32_t cvt_tf32(float f) {
    uint32_t u;
    asm("cvt.rna.tf32.f32 %0, %1;" : "=r"(u) : "f"(f));
    return u;
}

__device__ __forceinline__ uint32_t smem_u32(const void* p) {
    uint32_t a;
    asm("{ .reg .u64 t; cvta.to.shared.u64 t, %1; cvt.u32.u64 %0, t; }" : "=r"(a) : "l"(p));
    return a;
}

__device__ __forceinline__ void mma_tf32(float* d, const uint32_t* a, const uint32_t* b) {
    asm volatile(
        "mma.sync.aligned.m16n8k8.row.col.f32.tf32.tf32.f32 "
        "{%0,%1,%2,%3}, {%4,%5,%6,%7}, {%8,%9}, {%0,%1,%2,%3};"
        : "+f"(d[0]), "+f"(d[1]), "+f"(d[2]), "+f"(d[3])
        : "r"(a[0]), "r"(a[1]), "r"(a[2]), "r"(a[3]), "r"(b[0]), "r"(b[1]));
}

__device__ __forceinline__ void cp_async16(uint32_t dst, const void* src) {
    asm volatile("cp.async.cg.shared.global [%0], [%1], 16;"
                 :: "r"(dst), "l"(src) : "memory");
}
#define CP_COMMIT() asm volatile("cp.async.commit_group;" ::: "memory")
#define CP_WAIT(n)  asm volatile("cp.async.wait_group %0;" :: "n"(n) : "memory")

// ---------------------------------------------------------------------------
// Kernel A (v4): LayerNorm + attention pooling, register-resident x,
// batched reduce-scatter warp reduction (31 shuffles for all 25 partials).
// (unchanged from R7 — 197 µs @ 76.8% DRAM)
// ---------------------------------------------------------------------------
__global__ __launch_bounds__(256) void ln_attn_v4_kernel(
    const float* __restrict__ x,
    const float* __restrict__ gamma,
    const float* __restrict__ beta,
    const float* __restrict__ attnW)
{
    __shared__ float s_red[8][26];
    __shared__ float s_k[8];
    __shared__ float s_K;

    const int tid  = threadIdx.x;
    const int w    = tid >> 5;
    const int lane = tid & 31;
    const size_t row = blockIdx.x;
    const int col = tid * 2;

    const float2* xr = reinterpret_cast<const float2*>(x + row * SEQ * HDIM);
    const float2 gv = *reinterpret_cast<const float2*>(gamma + col);
    const float2 wn = *reinterpret_cast<const float2*>(attnW + HDIM + col);
    const float2 gw = make_float2(gv.x * wn.x, gv.y * wn.y);

    float2 xv[SEQ];
    float vals[32];
    #pragma unroll
    for (int t = 0; t < SEQ; t++) {
        const float2 v = xr[t * (HDIM / 2) + tid];
        xv[t] = v;
        vals[t]      = v.x + v.y;
        vals[8 + t]  = v.x * v.x + v.y * v.y;
        vals[16 + t] = gw.x * v.x + gw.y * v.y;
    }
    vals[24] = gw.x + gw.y;
    #pragma unroll
    for (int j = 25; j < 32; j++) vals[j] = 0.f;

    #pragma unroll
    for (int bit = 16; bit >= 1; bit >>= 1) {
        #pragma unroll
        for (int j = 0; j < bit; j++) {
            const bool hi = (lane & bit) != 0;
            const float keep = hi ? vals[j + bit] : vals[j];
            const float send = hi ? vals[j] : vals[j + bit];
            vals[j] = keep + __shfl_xor_sync(0xffffffffu, send, bit);
        }
    }

    if (lane < 25) s_red[w][lane] = vals[0];
    __syncthreads();

    if (w == 0) {
        float v = 0.f;
        if (lane < 25) {
            #pragma unroll
            for (int wi = 0; wi < 8; wi++) v += s_red[wi][lane];
        }
        const int t = lane & 7;
        const float S  = __shfl_sync(0xffffffffu, v, t);
        const float Q  = __shfl_sync(0xffffffffu, v, 8 + t);
        const float P  = __shfl_sync(0xffffffffu, v, 16 + t);
        const float S1 = __shfl_sync(0xffffffffu, v, 24);

        const float m    = S * (1.f / HDIM);
        const float var  = Q * (1.f / HDIM) - m * m;
        const float rstd = rsqrtf(var + LN_EPS);

        float logit = (lane >= 1 && lane < 8) ? rstd * (P - m * S1) : -1e30f;

        float mx = logit;
        mx = fmaxf(mx, __shfl_xor_sync(0xffffffffu, mx, 1));
        mx = fmaxf(mx, __shfl_xor_sync(0xffffffffu, mx, 2));
        mx = fmaxf(mx, __shfl_xor_sync(0xffffffffu, mx, 4));
        const float e = __expf(logit - mx);
        float se = e;
        se += __shfl_xor_sync(0xffffffffu, se, 1);
        se += __shfl_xor_sync(0xffffffffu, se, 2);
        se += __shfl_xor_sync(0xffffffffu, se, 4);
        const float a = e / se;

        const float k = (lane == 0) ? rstd : a * rstd;
        float Km = k * m;
        Km += __shfl_xor_sync(0xffffffffu, Km, 1);
        Km += __shfl_xor_sync(0xffffffffu, Km, 2);
        Km += __shfl_xor_sync(0xffffffffu, Km, 4);

        if (lane < 8) s_k[lane] = k;
        if (lane == 0) s_K = Km;
    }
    __syncthreads();

    const float Kc = s_K;
    float2 acc = make_float2(0.f, 0.f);
    #pragma unroll
    for (int t = 0; t < SEQ; t++) {
        const float k = s_k[t];
        acc.x += k * xv[t].x;
        acc.y += k * xv[t].y;
    }
    const float2 bv = *reinterpret_cast<const float2*>(beta + col);
    uint2 o;
    o.x = cvt_tf32(gv.x * (acc.x - Kc) + 2.f * bv.x);
    o.y = cvt_tf32(gv.y * (acc.y - Kc) + 2.f * bv.y);
    *reinterpret_cast<uint2*>(&g_fused[row * HDIM + col]) = o;
}

// ---------------------------------------------------------------------------
// Transpose out_W [512,256] -> g_Bt [256,512], tf32-rounded.
// ---------------------------------------------------------------------------
__global__ __launch_bounds__(256) void transpose_B_kernel(const float* __restrict__ B) {
    __shared__ float tile[32][33];
    const int n0 = blockIdx.x * 32;
    const int k0 = blockIdx.y * 32;
    const int tx = threadIdx.x & 31;
    const int ty = threadIdx.x >> 5;
    #pragma unroll
    for (int i = 0; i < 32; i += 8)
        tile[ty + i][tx] = B[(size_t)(k0 + ty + i) * HOUT + n0 + tx];
    __syncthreads();
    #pragma unroll
    for (int i = 0; i < 32; i += 8) {
        float v = tile[tx][ty + i];
        g_Bt[(size_t)(n0 + ty + i) * HDIM + k0 + tx] = __uint_as_float(cvt_tf32(v));
    }
}

// ---------------------------------------------------------------------------
// Kernel B (v4): C = relu(A @ Bt^T + bias) via mma.sync.m16n8k8.tf32.
// CTA 128x128, BK=32, STAGES=3 cp.async pipeline — canonical single-barrier
// multistage: one __syncthreads per chunk, loads issued BEFORE compute into
// the slot freed in the previous iteration. Fully unrolled mainloop.
// ---------------------------------------------------------------------------
#define BM 128
#define BN 128
#define BK 32
#define STAGES 3
#define A_STAGE_FLOATS (BM * BK)
#define B_STAGE_FLOATS (BN * BK)
#define STAGE_FLOATS   (A_STAGE_FLOATS + B_STAGE_FLOATS)
#define GEMM_SMEM      (STAGES * STAGE_FLOATS * 4)
#define NCH            (HDIM / BK)     // 16

__device__ __forceinline__ int swz_unit(int row, int u) {
    return row * 8 + (u ^ ((row & 1) << 2));
}

__global__ __launch_bounds__(256, 2) void gemm_v4_kernel(
    const float* __restrict__ bias,
    float* __restrict__ C)
{
    extern __shared__ float smem[];

    const int tid  = threadIdx.x;
    const int lane = tid & 31;
    const int wid  = tid >> 5;
    const int warp_m = wid & 3;
    const int warp_n = wid >> 2;
    const int g  = lane >> 2;
    const int tg = lane & 3;

    const int bn = blockIdx.x;
    const int bm = blockIdx.y;

    const float* Ag = g_fused + (size_t)bm * BM * HDIM;
    const float* Bg = g_Bt + (size_t)bn * BN * HDIM;

    const uint32_t smem_base = smem_u32(smem);

    const int st_row = tid >> 1;
    const int st_ub  = (tid & 1) * 4;

    float acc[2][8][4];
    #pragma unroll
    for (int mt = 0; mt < 2; mt++)
        #pragma unroll
        for (int nt = 0; nt < 8; nt++)
            #pragma unroll
            for (int i = 0; i < 4; i++) acc[mt][nt][i] = 0.f;

    auto stage_chunk = [&](int kchunk, int st) {
        const uint32_t sA = smem_base + (uint32_t)(st * STAGE_FLOATS) * 4u;
        const uint32_t sB = sA + A_STAGE_FLOATS * 4u;
        const float* srcA = Ag + (size_t)st_row * HDIM + kchunk * BK + st_ub * 4;
        const float* srcB = Bg + (size_t)st_row * HDIM + kchunk * BK + st_ub * 4;
        #pragma unroll
        for (int j = 0; j < 4; j++)
            cp_async16(sA + (uint32_t)swz_unit(st_row, st_ub + j) * 16u, srcA + j * 4);
        #pragma unroll
        for (int j = 0; j < 4; j++)
            cp_async16(sB + (uint32_t)swz_unit(st_row, st_ub + j) * 16u, srcB + j * 4);
    };

    // Prologue: stage chunks 0,1 (STAGES-1 groups in flight).
    stage_chunk(0, 0); CP_COMMIT();
    stage_chunk(1, 1); CP_COMMIT();

    #pragma unroll
    for (int k = 0; k < NCH; k++) {
        const int cur = k % STAGES;

        // Wait for chunk k (newest pending group is chunk k+1).
        CP_WAIT(1);
        __syncthreads();   // all warps finished reading slot (k+2)%3 in iter k-1

        // Issue loads for chunk k+2 into the freed slot, then commit.
        if (k + 2 < NCH) stage_chunk(k + 2, (k + 2) % STAGES);
        CP_COMMIT();

        // Compute chunk k.
        const float* Abuf = smem + cur * STAGE_FLOATS;
        const float* Bbuf = Abuf + A_STAGE_FLOATS;

        #pragma unroll
        for (int s = 0; s < 2; s++) {
            uint32_t af[4][4];
            #pragma unroll
            for (int mt = 0; mt < 2; mt++) {
                #pragma unroll
                for (int h = 0; h < 2; h++) {
                    const int r = warp_m * 32 + mt * 16 + g + h * 8;
                    const float4 v = *reinterpret_cast<const float4*>(
                        Abuf + swz_unit(r, s * 4 + tg) * 4);
                    af[mt * 2 + h][0] = __float_as_uint(v.x);
                    af[mt * 2 + h][1] = __float_as_uint(v.y);
                    af[mt * 2 + h][2] = __float_as_uint(v.z);
                    af[mt * 2 + h][3] = __float_as_uint(v.w);
                }
            }
            #pragma unroll
            for (int half = 0; half < 2; half++) {
                uint32_t bf[4][4];
                #pragma unroll
                for (int q = 0; q < 4; q++) {
                    const int n = warp_n * 64 + (half * 4 + q) * 8 + g;
                    const float4 v = *reinterpret_cast<const float4*>(
                        Bbuf + swz_unit(n, s * 4 + tg) * 4);
                    bf[q][0] = __float_as_uint(v.x);
                    bf[q][1] = __float_as_uint(v.y);
                    bf[q][2] = __float_as_uint(v.z);
                    bf[q][3] = __float_as_uint(v.w);
                }
                #pragma unroll
                for (int mt = 0; mt < 2; mt++) {
                    #pragma unroll
                    for (int q = 0; q < 4; q++) {
                        const int nt = half * 4 + q;
                        uint32_t a0[4] = { af[mt*2][0], af[mt*2+1][0],
                                           af[mt*2][1], af[mt*2+1][1] };
                        uint32_t b0[2] = { bf[q][0], bf[q][1] };
                        mma_tf32(acc[mt][nt], a0, b0);
                        uint32_t a1[4] = { af[mt*2][2], af[mt*2+1][2],
                                           af[mt*2][3], af[mt*2+1][3] };
                        uint32_t b1[2] = { bf[q][2], bf[q][3] };
                        mma_tf32(acc[mt][nt], a1, b1);
                    }
                }
            }
        }
    }

    // Epilogue: bias + relu.
    const int row_base = bm * BM + warp_m * 32;
    const int col_base = bn * BN + warp_n * 64;
    #pragma unroll
    for (int mt = 0; mt < 2; mt++) {
        #pragma unroll
        for (int nt = 0; nt < 8; nt++) {
            const int r0 = row_base + mt * 16 + g;
            const int c0 = col_base + nt * 8 + 2 * tg;
            const float2 bb = *reinterpret_cast<const float2*>(bias + c0);
            float2 o0, o1;
            o0.x = fmaxf(acc[mt][nt][0] + bb.x, 0.f);
            o0.y = fmaxf(acc[mt][nt][1] + bb.y, 0.f);
            o1.x = fmaxf(acc[mt][nt][2] + bb.x, 0.f);
            o1.y = fmaxf(acc[mt][nt][3] + bb.y, 0.f);
            *reinterpret_cast<float2*>(C + (size_t)r0 * HOUT + c0) = o0;
            *reinterpret_cast<float2*>(C + (size_t)(r0 + 8) * HOUT + c0) = o1;
        }
    }
}

// ---------------------------------------------------------------------------
extern "C" void kernel_launch(void* const* d_in, const int* in_sizes, int n_in,
                              void* d_out, int out_size) {
    const float* x     = (const float*)d_in[0];   // [N, 8, 512]
    const float* gamma = (const float*)d_in[1];   // [512]
    const float* beta  = (const float*)d_in[2];   // [512]
    const float* attnW = (const float*)d_in[3];   // [1024, 1]
    // d_in[4] = attn_b: cancels in softmax.
    const float* outW  = (const float*)d_in[5];   // [512, 256]
    const float* outb  = (const float*)d_in[6];   // [256]
    float* out = (float*)d_out;                   // [N, 256]

    const int n = in_sizes[0] / (SEQ * HDIM);

    cudaFuncSetAttribute(gemm_v4_kernel,
                         cudaFuncAttributeMaxDynamicSharedMemorySize, GEMM_SMEM);

    ln_attn_v4_kernel<<<n, 256>>>(x, gamma, beta, attnW);
    transpose_B_kernel<<<dim3(HOUT / 32, HDIM / 32), 256>>>(outW);

    dim3 grid(HOUT / BN, n / BM);
    gemm_v4_kernel<<<grid, 256, GEMM_SMEM>>>(outb, out);
}